// round 10
// baseline (speedup 1.0000x reference)
#include <cuda_runtime.h>
#include <math.h>

#define B 32
#define N 2048
#define BN (B*N)

// chamfer config (R6-proven shape)
#define CTHREADS 128
#define QPT 8
#define QPB (CTHREADS*QPT)       // 1024 queries per block
#define QCHUNKS 2                // N / QPB
#define DCHUNKS 8
#define DTILE (N/DCHUNKS)        // 256
#define BLKS_PER_DB (QCHUNKS*DCHUNKS)   // 16 blocks feed one (dir,b)

// prep config
#define PBLOCKS 256              // B * 8 segments
#define PTHREADS 256

typedef unsigned long long u64;

// ---------------- scratch (device globals; zero at module load) -------------
__device__ float2 g_Pxy[BN], g_Txy[BN];
__device__ float  g_Pnq[BN], g_Tnq[BN];  // |p|^2 if visible else -1
__device__ unsigned g_minbits[2*BN];     // per-(dir,b,q) min d2 bits
__device__ float g_ppart[PBLOCKS*5];     // {point,mask,struct,cntP,cntT}
__device__ float g_chsum[2*B];           // per-(dir,b) sqrt-sums
__device__ int   g_dbticket[2*B];        // per-(dir,b) arrival counters
__device__ int   g_fticket;              // combine ticket

// ---------------- packed f32x2 helpers --------------------------------------
__device__ __forceinline__ u64 pack2(float lo, float hi) {
    u64 r; asm("mov.b64 %0,{%1,%2};" : "=l"(r) : "f"(lo), "f"(hi)); return r;
}
__device__ __forceinline__ u64 fma2(u64 a, u64 b, u64 c) {
    u64 d; asm("fma.rn.f32x2 %0,%1,%2,%3;" : "=l"(d) : "l"(a), "l"(b), "l"(c)); return d;
}
__device__ __forceinline__ void unpack2(u64 v, float& lo, float& hi) {
    asm("mov.b64 {%0,%1},%2;" : "=f"(lo), "=f"(hi) : "l"(v));
}

// ---------------- prep: pure map (no atomics) + partials ---------------------
__global__ void __launch_bounds__(PTHREADS) sk_prep_kernel(
        const float* __restrict__ pred,
        const float* __restrict__ target,
        const float* __restrict__ smask) {
    int bx = blockIdx.x;
    int b = bx >> 3, seg = bx & 7;
    int n = seg * PTHREADS + threadIdx.x;
    int idx = b * N + n;
    int lane = threadIdx.x & 31, wid = threadIdx.x >> 5;
    __shared__ float red[40];   // 8 warps x 5

    float p0 = pred[idx*3+0],  p1 = pred[idx*3+1],  p2 = pred[idx*3+2];
    float t0 = target[idx*3+0], t1 = target[idx*3+1], t2 = target[idx*3+2];
    bool tv = (t2 == 1.0f);
    bool pv = (p2 == 1.0f);

    float s_point = 0.f, s_mask = 0.f, s_struct = 0.f;
    if (tv) {
        float d0 = p0 - t0, d1 = p1 - t1;
        s_point = d0*d0 + d1*d1;
        float m0 = smask[idx*2+0], m1 = smask[idx*2+1];
        float sm = fminf(fmaxf(m0 + m1, 0.f), 1.f);
        s_mask = sm;
        float e0 = d0 * sm, e1 = d1 * sm;
        s_struct = e0*e0 + e1*e1;
    }

    float px = pv ? p0 : 0.f, py = pv ? p1 : 0.f;
    float tx = tv ? t0 : 0.f, ty = tv ? t1 : 0.f;
    float np = px*px + py*py, nt = tx*tx + ty*ty;
    g_Pxy[idx] = make_float2(px, py);
    g_Pnq[idx] = pv ? np : -1.f;
    g_Txy[idx] = make_float2(tx, ty);
    g_Tnq[idx] = tv ? nt : -1.f;

    // fresh min slots each replay
    g_minbits[(0*B + b)*N + n] = 0x7F7FFFFFu;
    g_minbits[(1*B + b)*N + n] = 0x7F7FFFFFu;

    float cp = pv ? 1.f : 0.f, ct = tv ? 1.f : 0.f;
    #pragma unroll
    for (int o = 16; o; o >>= 1) {
        s_point  += __shfl_xor_sync(0xffffffffu, s_point,  o);
        s_mask   += __shfl_xor_sync(0xffffffffu, s_mask,   o);
        s_struct += __shfl_xor_sync(0xffffffffu, s_struct, o);
        cp       += __shfl_xor_sync(0xffffffffu, cp,       o);
        ct       += __shfl_xor_sync(0xffffffffu, ct,       o);
    }
    if (lane == 0) {
        red[wid] = s_point; red[8+wid] = s_mask; red[16+wid] = s_struct;
        red[24+wid] = cp; red[32+wid] = ct;
    }
    __syncthreads();
    if (threadIdx.x == 0) {
        float a=0.f,c=0.f,d=0.f,e=0.f,f=0.f;
        #pragma unroll
        for (int w = 0; w < 8; w++) {
            a += red[w]; c += red[8+w]; d += red[16+w];
            e += red[24+w]; f += red[32+w];
        }
        g_ppart[bx*5+0]=a; g_ppart[bx*5+1]=c; g_ppart[bx*5+2]=d;
        g_ppart[bx*5+3]=e; g_ppart[bx*5+4]=f;
    }
}

// ---------------- chamfer + fused reductions ---------------------------------
__global__ void __launch_bounds__(CTHREADS) sk_chamfer_kernel(float* __restrict__ out) {
    int qchunk = blockIdx.x, b = blockIdx.y;
    int dir = blockIdx.z >> 3, dchunk = blockIdx.z & 7;
    int db = dir * B + b;
    int tid = threadIdx.x;

    const float2 *Qxy, *Dxy;
    const float *Qnq, *Dnq;
    if (dir == 0) {
        Qxy = g_Pxy + b*N; Qnq = g_Pnq + b*N;
        Dxy = g_Txy + b*N; Dnq = g_Tnq + b*N;
    } else {
        Qxy = g_Txy + b*N; Qnq = g_Tnq + b*N;
        Dxy = g_Pxy + b*N; Dnq = g_Pnq + b*N;
    }

    __shared__ __align__(16) u64 sxx[DTILE];   // {-2x,-2x} dup, 2 KB
    __shared__ __align__(16) u64 syy[DTILE];   // {-2y,-2y} dup, 2 KB
    __shared__ __align__(16) u64 snn[DTILE];   // {n,n} dup (BIG if invisible), 2 KB

    int dstart = dchunk * DTILE;
    #pragma unroll
    for (int it = 0; it < DTILE / CTHREADS; it++) {
        int j = it * CTHREADS + tid;
        int g = dstart + j;
        float2 dpt = Dxy[g];
        float nq = Dnq[g];
        float x = -2.0f * dpt.x, y = -2.0f * dpt.y;
        float n2 = (nq < 0.f) ? 3.0e38f : nq;
        sxx[j] = pack2(x, x);
        syy[j] = pack2(y, y);
        snn[j] = pack2(n2, n2);
    }

    int qbase = qchunk * QPB;
    u64 px2[QPT/2], py2[QPT/2];
    float mm[QPT];
    #pragma unroll
    for (int k = 0; k < QPT/2; k++) {
        int q0 = qbase + (2*k)   * CTHREADS + tid;
        int q1 = qbase + (2*k+1) * CTHREADS + tid;
        float2 a = Qxy[q0], c = Qxy[q1];
        px2[k] = pack2(a.x, c.x);
        py2[k] = pack2(a.y, c.y);
        mm[2*k] = 3.0e38f; mm[2*k+1] = 3.0e38f;
    }
    __syncthreads();

    // 4-wide j-groups: 6 LDS.128, flat 8-value tournament per k
    #pragma unroll 1
    for (int j = 0; j < DTILE; j += 4) {
        ulonglong2 xxA = *reinterpret_cast<const ulonglong2*>(&sxx[j]);
        ulonglong2 xxB = *reinterpret_cast<const ulonglong2*>(&sxx[j+2]);
        ulonglong2 yyA = *reinterpret_cast<const ulonglong2*>(&syy[j]);
        ulonglong2 yyB = *reinterpret_cast<const ulonglong2*>(&syy[j+2]);
        ulonglong2 nnA = *reinterpret_cast<const ulonglong2*>(&snn[j]);
        ulonglong2 nnB = *reinterpret_cast<const ulonglong2*>(&snn[j+2]);
        #pragma unroll
        for (int k = 0; k < QPT/2; k++) {
            u64 d0 = fma2(px2[k], xxA.x, fma2(py2[k], yyA.x, nnA.x));
            u64 d1 = fma2(px2[k], xxA.y, fma2(py2[k], yyA.y, nnA.y));
            u64 d2 = fma2(px2[k], xxB.x, fma2(py2[k], yyB.x, nnB.x));
            u64 d3 = fma2(px2[k], xxB.y, fma2(py2[k], yyB.y, nnB.y));
            float l0, h0, l1, h1, l2, h2, l3, h3;
            unpack2(d0, l0, h0);
            unpack2(d1, l1, h1);
            unpack2(d2, l2, h2);
            unpack2(d3, l3, h3);
            float a01 = fminf(l0, l1), a23 = fminf(l2, l3);
            float b01 = fminf(h0, h1), b23 = fminf(h2, h3);
            mm[2*k]   = fminf(mm[2*k],   fminf(a01, a23));
            mm[2*k+1] = fminf(mm[2*k+1], fminf(b01, b23));
        }
    }

    unsigned* minb = g_minbits + db * N;
    #pragma unroll
    for (int i = 0; i < QPT; i++) {
        int q = qbase + i * CTHREADS + tid;
        float v = fmaxf(Qnq[q] + mm[i], 1e-12f);   // clamp keeps bits monotone
        atomicMin(&minb[q], __float_as_uint(v));
    }

    // ---- ticket 1: last block of this (dir,b) does the sqrt-sum -------------
    __shared__ int s_tkt;
    __shared__ float wred[4];
    if (tid == 0) {
        __threadfence();
        s_tkt = atomicAdd(&g_dbticket[db], 1);
    }
    __syncthreads();
    if (s_tkt != BLKS_PER_DB - 1) return;
    if (tid == 0) g_dbticket[db] = 0;      // reset for next replay
    __threadfence();

    float s = 0.f;
    #pragma unroll
    for (int it = 0; it < N / CTHREADS; it++) {
        int q = it * CTHREADS + tid;
        unsigned mb = g_minbits[db * N + q];
        if (Qnq[q] >= 0.f) s += sqrtf(__uint_as_float(mb));
    }
    #pragma unroll
    for (int o = 16; o; o >>= 1) s += __shfl_xor_sync(0xffffffffu, s, o);
    if ((tid & 31) == 0) wred[tid >> 5] = s;
    __syncthreads();

    __shared__ int s_ft;
    if (tid == 0) {
        g_chsum[db] = wred[0] + wred[1] + wred[2] + wred[3];
        __threadfence();
        s_ft = atomicAdd(&g_fticket, 1);
    }
    __syncthreads();
    if (s_ft != 2*B - 1) return;
    if (tid == 0) g_fticket = 0;
    __threadfence();

    // ---- ticket 2 winner: scalar combine ------------------------------------
    __shared__ float sred[12];   // 4 warps x 3
    __shared__ float sb[2*B];    // per-b cntP / cntT
    volatile float* vch = g_chsum;

    float sp = 0.f, smk = 0.f, sst = 0.f;
    #pragma unroll
    for (int it = 0; it < PBLOCKS / CTHREADS; it++) {
        int blk = it * CTHREADS + tid;
        sp  += g_ppart[blk*5+0];
        smk += g_ppart[blk*5+1];
        sst += g_ppart[blk*5+2];
    }
    #pragma unroll
    for (int o = 16; o; o >>= 1) {
        sp  += __shfl_xor_sync(0xffffffffu, sp,  o);
        smk += __shfl_xor_sync(0xffffffffu, smk, o);
        sst += __shfl_xor_sync(0xffffffffu, sst, o);
    }
    if ((tid & 31) == 0) { int w = tid >> 5; sred[w]=sp; sred[4+w]=smk; sred[8+w]=sst; }

    if (tid < 2*B) {                         // per-b counts
        int bb = tid & 31, which = (tid < B) ? 3 : 4;
        float c = 0.f;
        #pragma unroll
        for (int seg = 0; seg < 8; seg++) c += g_ppart[(bb*8+seg)*5 + which];
        sb[tid] = c;
    }
    __syncthreads();

    float ch = 0.f;
    if (tid < B) {
        float cp = sb[tid], ct = sb[B + tid];
        float mp = vch[tid]     / fmaxf(cp, 1.f);   // dir0: queries = preds
        float mt = vch[B + tid] / fmaxf(ct, 1.f);   // dir1: queries = targets
        ch = (cp > 0.f && ct > 0.f) ? 0.5f * (mp + mt) : 0.f;
    }
    #pragma unroll
    for (int o = 16; o; o >>= 1) ch += __shfl_xor_sync(0xffffffffu, ch, o);

    if (tid == 0) {
        float a = 0.f, c = 0.f, d = 0.f;
        #pragma unroll
        for (int w = 0; w < 4; w++) { a += sred[w]; c += sred[4+w]; d += sred[8+w]; }
        float lc = ch / (float)B;
        float lp = a / (float)(B * N * 2);
        float ls = (c > 0.f) ? d / (float)(B * N * 2) : 0.f;
        out[0] = lp + 5.0f * lc + 2.0f * ls;
        out[1] = lp;
        out[2] = 0.f;
        out[3] = lc;
    }
}

extern "C" void kernel_launch(void* const* d_in, const int* in_sizes, int n_in,
                              void* d_out, int out_size) {
    const float* pred   = (const float*)d_in[0];
    const float* target = (const float*)d_in[1];
    const float* smask  = (const float*)d_in[2];
    float* out = (float*)d_out;

    sk_prep_kernel<<<PBLOCKS, PTHREADS>>>(pred, target, smask);
    dim3 cgrid(QCHUNKS, B, 2 * DCHUNKS);
    sk_chamfer_kernel<<<cgrid, CTHREADS>>>(out);
}

// round 12
// speedup vs baseline: 1.4567x; 1.4567x over previous
#include <cuda_runtime.h>
#include <math.h>

#define B 32
#define N 2048
#define BN (B*N)

// binning
#define G 32
#define GG (G*G)
#define ORG  (-4.5f)
#define WBIN (9.0f / (float)G)
#define INVW ((float)G / 9.0f)

#define ATHREADS 256
#define QC 4                      // query chunks per (dir,b)
#define STHREADS 256
#define SBLOCKS (QC*B*2)          // 256 search blocks

// ---------------- scratch (device globals; zero at module load) -------------
__device__ float2 g_Pb[BN], g_Tb[BN];        // binned visible points (CSR data)
__device__ int    g_offP[B*1025], g_offT[B*1025];  // CSR offsets + total at [1024]
__device__ float  g_ppart[B*3];              // {point,mask,struct} per batch
__device__ float  g_chpart[2*B*QC];          // per (dir,b,qc) sqrt-sums
__device__ int    g_fticket;                 // combine ticket (winner resets)

__device__ __forceinline__ int binc(float x) {
    int i = (int)floorf((x - ORG) * INVW);
    return min(max(i, 0), G - 1);
}

// exclusive scan of 1024 smem counters; writes offsets in place + to global[0..1024]
__device__ __forceinline__ void scan1024(unsigned* arr, unsigned* wsum, int* gout, int tid) {
    __syncthreads();
    int lane = tid & 31, wid = tid >> 5;
    unsigned v0 = arr[tid*4+0], v1 = arr[tid*4+1], v2 = arr[tid*4+2], v3 = arr[tid*4+3];
    unsigned tsum = v0 + v1 + v2 + v3;
    unsigned pre = tsum;
    #pragma unroll
    for (int o = 1; o < 32; o <<= 1) {
        unsigned nv = __shfl_up_sync(0xffffffffu, pre, o);
        if (lane >= o) pre += nv;
    }
    if (lane == 31) wsum[wid] = pre;
    unsigned texcl = pre - tsum;
    __syncthreads();
    if (tid == 0) {
        unsigned acc = 0;
        for (int w = 0; w < 8; w++) { unsigned x = wsum[w]; wsum[w] = acc; acc += x; }
        wsum[8] = acc;
    }
    __syncthreads();
    unsigned off = wsum[wid] + texcl;
    arr[tid*4+0] = off;      gout[tid*4+0] = (int)off;      off += v0;
    arr[tid*4+1] = off;      gout[tid*4+1] = (int)off;      off += v1;
    arr[tid*4+2] = off;      gout[tid*4+2] = (int)off;      off += v2;
    arr[tid*4+3] = off;      gout[tid*4+3] = (int)off;
    if (tid == 0) gout[1024] = (int)wsum[8];
    __syncthreads();
}

// ---------------- kernel A: losses + bin count + scan + scatter --------------
__global__ void __launch_bounds__(ATHREADS) sk_bin_kernel(
        const float* __restrict__ pred,
        const float* __restrict__ target,
        const float* __restrict__ smask) {
    int b = blockIdx.x, tid = threadIdx.x;
    __shared__ unsigned s_cnt[2*GG];   // P counts then T counts (8 KB)
    __shared__ unsigned s_wsum[9];
    __shared__ float red[24];          // 8 warps x 3

    for (int i = tid; i < 2*GG; i += ATHREADS) s_cnt[i] = 0;
    __syncthreads();

    float s_point = 0.f, s_mask = 0.f, s_struct = 0.f;
    #pragma unroll
    for (int it = 0; it < N/ATHREADS; it++) {
        int n = it * ATHREADS + tid;
        int idx = b * N + n;
        float p0 = pred[idx*3+0],  p1 = pred[idx*3+1],  p2 = pred[idx*3+2];
        float t0 = target[idx*3+0], t1 = target[idx*3+1], t2 = target[idx*3+2];
        bool tv = (t2 == 1.0f), pv = (p2 == 1.0f);
        if (tv) {
            float d0 = p0 - t0, d1 = p1 - t1;
            s_point += d0*d0 + d1*d1;
            float m0 = smask[idx*2+0], m1 = smask[idx*2+1];
            float sm = fminf(fmaxf(m0 + m1, 0.f), 1.f);
            s_mask += sm;
            float e0 = d0*sm, e1 = d1*sm;
            s_struct += e0*e0 + e1*e1;
            atomicAdd(&s_cnt[GG + binc(t1)*G + binc(t0)], 1u);
        }
        if (pv) atomicAdd(&s_cnt[binc(p1)*G + binc(p0)], 1u);
    }

    scan1024(s_cnt,      s_wsum, g_offP + b*1025, tid);
    scan1024(s_cnt + GG, s_wsum, g_offT + b*1025, tid);

    // scatter (smem offsets post-incremented)
    #pragma unroll
    for (int it = 0; it < N/ATHREADS; it++) {
        int n = it * ATHREADS + tid;
        int idx = b * N + n;
        float p0 = pred[idx*3+0],  p1 = pred[idx*3+1],  p2 = pred[idx*3+2];
        float t0 = target[idx*3+0], t1 = target[idx*3+1], t2 = target[idx*3+2];
        if (p2 == 1.0f) {
            unsigned slot = atomicAdd(&s_cnt[binc(p1)*G + binc(p0)], 1u);
            g_Pb[b*N + slot] = make_float2(p0, p1);
        }
        if (t2 == 1.0f) {
            unsigned slot = atomicAdd(&s_cnt[GG + binc(t1)*G + binc(t0)], 1u);
            g_Tb[b*N + slot] = make_float2(t0, t1);
        }
    }

    // loss partials
    #pragma unroll
    for (int o = 16; o; o >>= 1) {
        s_point  += __shfl_xor_sync(0xffffffffu, s_point,  o);
        s_mask   += __shfl_xor_sync(0xffffffffu, s_mask,   o);
        s_struct += __shfl_xor_sync(0xffffffffu, s_struct, o);
    }
    int lane = tid & 31, wid = tid >> 5;
    if (lane == 0) { red[wid] = s_point; red[8+wid] = s_mask; red[16+wid] = s_struct; }
    __syncthreads();
    if (tid == 0) {
        float a = 0.f, c = 0.f, d = 0.f;
        for (int w = 0; w < 8; w++) { a += red[w]; c += red[8+w]; d += red[16+w]; }
        g_ppart[b*3+0] = a; g_ppart[b*3+1] = c; g_ppart[b*3+2] = d;
    }
}

// ---------------- kernel B: ring search + fused combine ----------------------
__global__ void __launch_bounds__(STHREADS) sk_search_kernel(float* __restrict__ out) {
    int qc = blockIdx.x, b = blockIdx.y, dir = blockIdx.z;
    int db = dir * B + b;
    int tid = threadIdx.x;

    const float2 *Qp, *Dp;
    const int *Qoff, *Doff;
    if (dir == 0) { Qp = g_Pb + b*N; Qoff = g_offP + b*1025; Dp = g_Tb + b*N; Doff = g_offT + b*1025; }
    else          { Qp = g_Tb + b*N; Qoff = g_offT + b*1025; Dp = g_Pb + b*N; Doff = g_offP + b*1025; }
    int cntQ = Qoff[1024];

    float sum = 0.f;
    #pragma unroll
    for (int sub = 0; sub < 2; sub++) {
        int q = qc * (2*STHREADS) + sub * STHREADS + tid;
        if (q < cntQ) {
            float2 Qv = Qp[q];
            int qbx = binc(Qv.x), qby = binc(Qv.y);
            float best = 3.0e38f;

            auto scan_span = [&](int s, int e) {
                for (int k = s; k < e; k++) {
                    float2 p = Dp[k];
                    float dx = Qv.x - p.x, dy = Qv.y - p.y;
                    float d2 = fmaf(dx, dx, dy*dy);
                    best = fminf(best, d2);
                }
            };

            for (int r = 0; r < G; r++) {
                if (r > 0) {
                    float bd = (float)(r-1) * WBIN;
                    if (best <= bd*bd) break;
                }
                int i0 = max(qbx - r, 0), i1 = min(qbx + r, G-1);
                if (r == 0) {
                    int base = qby*G + qbx;
                    scan_span(Doff[base], Doff[base+1]);
                } else {
                    int jt = qby - r, jb = qby + r;
                    if (jt >= 0) scan_span(Doff[jt*G + i0], Doff[jt*G + i1 + 1]);
                    if (jb < G)  scan_span(Doff[jb*G + i0], Doff[jb*G + i1 + 1]);
                    int jj0 = max(qby - r + 1, 0), jj1 = min(qby + r - 1, G-1);
                    if (qbx - r >= 0) {
                        int ic = qbx - r;
                        for (int j = jj0; j <= jj1; j++) scan_span(Doff[j*G + ic], Doff[j*G + ic + 1]);
                    }
                    if (qbx + r < G) {
                        int ic = qbx + r;
                        for (int j = jj0; j <= jj1; j++) scan_span(Doff[j*G + ic], Doff[j*G + ic + 1]);
                    }
                }
            }
            sum += sqrtf(fmaxf(best, 1e-12f));
        }
    }

    // block reduction of sqrt-sum
    __shared__ float wred[8];
    #pragma unroll
    for (int o = 16; o; o >>= 1) sum += __shfl_xor_sync(0xffffffffu, sum, o);
    if ((tid & 31) == 0) wred[tid >> 5] = sum;
    __syncthreads();

    __shared__ int s_ft;
    if (tid == 0) {
        float tot = 0.f;
        #pragma unroll
        for (int w = 0; w < 8; w++) tot += wred[w];
        g_chpart[db*QC + qc] = tot;
        __threadfence();
        s_ft = atomicAdd(&g_fticket, 1);
    }
    __syncthreads();
    if (s_ft != SBLOCKS - 1) return;
    if (tid == 0) g_fticket = 0;          // reset for next replay
    __threadfence();

    // ---- combine (winner block) ---------------------------------------------
    __shared__ float s_ch[2*B];
    volatile float* vcp = g_chpart;
    if (tid < 2*B) {
        float s = 0.f;
        #pragma unroll
        for (int c = 0; c < QC; c++) s += vcp[tid*QC + c];
        s_ch[tid] = s;
    }
    __syncthreads();

    float ch = 0.f, a = 0.f, c = 0.f, d = 0.f;
    if (tid < B) {
        float cp = (float)g_offP[tid*1025 + 1024];
        float ct = (float)g_offT[tid*1025 + 1024];
        float mp = s_ch[tid]     / fmaxf(cp, 1.f);   // dir0: queries = preds
        float mt = s_ch[B + tid] / fmaxf(ct, 1.f);   // dir1: queries = targets
        ch = (cp > 0.f && ct > 0.f) ? 0.5f * (mp + mt) : 0.f;
        a = g_ppart[tid*3+0]; c = g_ppart[tid*3+1]; d = g_ppart[tid*3+2];
    }
    if (tid < 32) {
        #pragma unroll
        for (int o = 16; o; o >>= 1) {
            ch += __shfl_xor_sync(0xffffffffu, ch, o);
            a  += __shfl_xor_sync(0xffffffffu, a,  o);
            c  += __shfl_xor_sync(0xffffffffu, c,  o);
            d  += __shfl_xor_sync(0xffffffffu, d,  o);
        }
        if (tid == 0) {
            float lc = ch / (float)B;
            float lp = a / (float)(B * N * 2);
            float ls = (c > 0.f) ? d / (float)(B * N * 2) : 0.f;
            out[0] = lp + 5.0f * lc + 2.0f * ls;
            out[1] = lp;
            out[2] = 0.f;
            out[3] = lc;
        }
    }
}

extern "C" void kernel_launch(void* const* d_in, const int* in_sizes, int n_in,
                              void* d_out, int out_size) {
    const float* pred   = (const float*)d_in[0];
    const float* target = (const float*)d_in[1];
    const float* smask  = (const float*)d_in[2];
    float* out = (float*)d_out;

    sk_bin_kernel<<<B, ATHREADS>>>(pred, target, smask);
    dim3 sgrid(QC, B, 2);
    sk_search_kernel<<<sgrid, STHREADS>>>(out);
}

// round 13
// speedup vs baseline: 2.0619x; 1.4154x over previous
#include <cuda_runtime.h>
#include <math.h>

#define B 32
#define N 2048
#define BN (B*N)

// binning
#define G 32
#define GG (G*G)
#define ORG  (-4.5f)
#define WBIN (9.0f / (float)G)
#define INVW ((float)G / 9.0f)

#define ATHREADS 256
#define QC 8                      // query chunks per (dir,b): 1 query/thread
#define STHREADS 256
#define SBLOCKS (QC*B*2)          // 512 search blocks

// ---------------- scratch (device globals; zero at module load) -------------
__device__ float2 g_Pb[BN], g_Tb[BN];        // binned visible points (CSR data)
__device__ int    g_offP[B*1025], g_offT[B*1025];  // CSR offsets + total at [1024]
__device__ float  g_ppart[B*3];              // {point,mask,struct} per batch
__device__ float  g_chpart[2*B*QC];          // per (dir,b,qc) sqrt-sums
__device__ int    g_fticket;                 // combine ticket (winner resets)

__device__ __forceinline__ int binc(float x) {
    int i = (int)floorf((x - ORG) * INVW);
    return min(max(i, 0), G - 1);
}

// exclusive scan of 1024 smem counters; writes offsets in place + to global[0..1024]
__device__ __forceinline__ void scan1024(unsigned* arr, unsigned* wsum, int* gout, int tid) {
    __syncthreads();
    int lane = tid & 31, wid = tid >> 5;
    unsigned v0 = arr[tid*4+0], v1 = arr[tid*4+1], v2 = arr[tid*4+2], v3 = arr[tid*4+3];
    unsigned tsum = v0 + v1 + v2 + v3;
    unsigned pre = tsum;
    #pragma unroll
    for (int o = 1; o < 32; o <<= 1) {
        unsigned nv = __shfl_up_sync(0xffffffffu, pre, o);
        if (lane >= o) pre += nv;
    }
    if (lane == 31) wsum[wid] = pre;
    unsigned texcl = pre - tsum;
    __syncthreads();
    if (tid == 0) {
        unsigned acc = 0;
        for (int w = 0; w < 8; w++) { unsigned x = wsum[w]; wsum[w] = acc; acc += x; }
        wsum[8] = acc;
    }
    __syncthreads();
    unsigned off = wsum[wid] + texcl;
    arr[tid*4+0] = off;      gout[tid*4+0] = (int)off;      off += v0;
    arr[tid*4+1] = off;      gout[tid*4+1] = (int)off;      off += v1;
    arr[tid*4+2] = off;      gout[tid*4+2] = (int)off;      off += v2;
    arr[tid*4+3] = off;      gout[tid*4+3] = (int)off;
    if (tid == 0) gout[1024] = (int)wsum[8];
    __syncthreads();
}

// ---------------- kernel A: losses + bin count + scan + scatter --------------
__global__ void __launch_bounds__(ATHREADS) sk_bin_kernel(
        const float* __restrict__ pred,
        const float* __restrict__ target,
        const float* __restrict__ smask) {
    int b = blockIdx.x, tid = threadIdx.x;
    __shared__ unsigned s_cnt[2*GG];   // P counts then T counts (8 KB)
    __shared__ unsigned s_wsum[9];
    __shared__ float red[24];          // 8 warps x 3

    for (int i = tid; i < 2*GG; i += ATHREADS) s_cnt[i] = 0;
    __syncthreads();

    float s_point = 0.f, s_mask = 0.f, s_struct = 0.f;
    #pragma unroll
    for (int it = 0; it < N/ATHREADS; it++) {
        int n = it * ATHREADS + tid;
        int idx = b * N + n;
        float p0 = pred[idx*3+0],  p1 = pred[idx*3+1],  p2 = pred[idx*3+2];
        float t0 = target[idx*3+0], t1 = target[idx*3+1], t2 = target[idx*3+2];
        bool tv = (t2 == 1.0f), pv = (p2 == 1.0f);
        if (tv) {
            float d0 = p0 - t0, d1 = p1 - t1;
            s_point += d0*d0 + d1*d1;
            float m0 = smask[idx*2+0], m1 = smask[idx*2+1];
            float sm = fminf(fmaxf(m0 + m1, 0.f), 1.f);
            s_mask += sm;
            float e0 = d0*sm, e1 = d1*sm;
            s_struct += e0*e0 + e1*e1;
            atomicAdd(&s_cnt[GG + binc(t1)*G + binc(t0)], 1u);
        }
        if (pv) atomicAdd(&s_cnt[binc(p1)*G + binc(p0)], 1u);
    }

    scan1024(s_cnt,      s_wsum, g_offP + b*1025, tid);
    scan1024(s_cnt + GG, s_wsum, g_offT + b*1025, tid);

    // scatter (smem offsets post-incremented)
    #pragma unroll
    for (int it = 0; it < N/ATHREADS; it++) {
        int n = it * ATHREADS + tid;
        int idx = b * N + n;
        float p0 = pred[idx*3+0],  p1 = pred[idx*3+1],  p2 = pred[idx*3+2];
        float t0 = target[idx*3+0], t1 = target[idx*3+1], t2 = target[idx*3+2];
        if (p2 == 1.0f) {
            unsigned slot = atomicAdd(&s_cnt[binc(p1)*G + binc(p0)], 1u);
            g_Pb[b*N + slot] = make_float2(p0, p1);
        }
        if (t2 == 1.0f) {
            unsigned slot = atomicAdd(&s_cnt[GG + binc(t1)*G + binc(t0)], 1u);
            g_Tb[b*N + slot] = make_float2(t0, t1);
        }
    }

    // loss partials
    #pragma unroll
    for (int o = 16; o; o >>= 1) {
        s_point  += __shfl_xor_sync(0xffffffffu, s_point,  o);
        s_mask   += __shfl_xor_sync(0xffffffffu, s_mask,   o);
        s_struct += __shfl_xor_sync(0xffffffffu, s_struct, o);
    }
    int lane = tid & 31, wid = tid >> 5;
    if (lane == 0) { red[wid] = s_point; red[8+wid] = s_mask; red[16+wid] = s_struct; }
    __syncthreads();
    if (tid == 0) {
        float a = 0.f, c = 0.f, d = 0.f;
        for (int w = 0; w < 8; w++) { a += red[w]; c += red[8+w]; d += red[16+w]; }
        g_ppart[b*3+0] = a; g_ppart[b*3+1] = c; g_ppart[b*3+2] = d;
    }
}

// ---------------- kernel B: smem-staged ring search + fused combine ----------
__global__ void __launch_bounds__(STHREADS) sk_search_kernel(float* __restrict__ out) {
    int qc = blockIdx.x, b = blockIdx.y, dir = blockIdx.z;
    int db = dir * B + b;
    int tid = threadIdx.x;

    const float2 *Qp, *Dp;
    const int *Qoff, *Doff;
    if (dir == 0) { Qp = g_Pb + b*N; Qoff = g_offP + b*1025; Dp = g_Tb + b*N; Doff = g_offT + b*1025; }
    else          { Qp = g_Tb + b*N; Qoff = g_offT + b*1025; Dp = g_Pb + b*N; Doff = g_offP + b*1025; }

    // stage whole database + offsets in shared memory
    __shared__ float2 s_D[N];        // 16 KB
    __shared__ int    s_off[1025];   // 4.1 KB
    #pragma unroll
    for (int it = 0; it < N/STHREADS; it++)
        s_D[it*STHREADS + tid] = Dp[it*STHREADS + tid];
    #pragma unroll
    for (int it = 0; it < 1025/STHREADS + 1; it++) {
        int i = it*STHREADS + tid;
        if (i < 1025) s_off[i] = Doff[i];
    }
    int cntQ = Qoff[1024];
    __syncthreads();

    float sum = 0.f;
    int q = qc * STHREADS + tid;
    if (q < cntQ) {
        float2 Qv = Qp[q];
        int qbx = binc(Qv.x), qby = binc(Qv.y);
        float best = 3.0e38f;

        auto scan_span = [&](int s, int e) {
            for (int k = s; k < e; k++) {
                float2 p = s_D[k];
                float dx = Qv.x - p.x, dy = Qv.y - p.y;
                float d2 = fmaf(dx, dx, dy*dy);
                best = fminf(best, d2);
            }
        };

        for (int r = 0; r < G; r++) {
            if (r > 0) {
                float bd = (float)(r-1) * WBIN;
                if (best <= bd*bd) break;
            }
            int i0 = max(qbx - r, 0), i1 = min(qbx + r, G-1);
            if (r == 0) {
                int base = qby*G + qbx;
                scan_span(s_off[base], s_off[base+1]);
            } else {
                int jt = qby - r, jb = qby + r;
                if (jt >= 0) scan_span(s_off[jt*G + i0], s_off[jt*G + i1 + 1]);
                if (jb < G)  scan_span(s_off[jb*G + i0], s_off[jb*G + i1 + 1]);
                int jj0 = max(qby - r + 1, 0), jj1 = min(qby + r - 1, G-1);
                if (qbx - r >= 0) {
                    int ic = qbx - r;
                    for (int j = jj0; j <= jj1; j++) scan_span(s_off[j*G + ic], s_off[j*G + ic + 1]);
                }
                if (qbx + r < G) {
                    int ic = qbx + r;
                    for (int j = jj0; j <= jj1; j++) scan_span(s_off[j*G + ic], s_off[j*G + ic + 1]);
                }
            }
        }
        sum = sqrtf(fmaxf(best, 1e-12f));
    }

    // block reduction of sqrt-sum
    __shared__ float wred[8];
    #pragma unroll
    for (int o = 16; o; o >>= 1) sum += __shfl_xor_sync(0xffffffffu, sum, o);
    if ((tid & 31) == 0) wred[tid >> 5] = sum;
    __syncthreads();

    __shared__ int s_ft;
    if (tid == 0) {
        float tot = 0.f;
        #pragma unroll
        for (int w = 0; w < 8; w++) tot += wred[w];
        g_chpart[db*QC + qc] = tot;
        __threadfence();
        s_ft = atomicAdd(&g_fticket, 1);
    }
    __syncthreads();
    if (s_ft != SBLOCKS - 1) return;
    if (tid == 0) g_fticket = 0;          // reset for next replay
    __threadfence();

    // ---- combine (winner block) ---------------------------------------------
    __shared__ float s_ch[2*B];
    volatile float* vcp = g_chpart;
    if (tid < 2*B) {
        float s = 0.f;
        #pragma unroll
        for (int c = 0; c < QC; c++) s += vcp[tid*QC + c];
        s_ch[tid] = s;
    }
    __syncthreads();

    float ch = 0.f, a = 0.f, c = 0.f, d = 0.f;
    if (tid < B) {
        float cp = (float)g_offP[tid*1025 + 1024];
        float ct = (float)g_offT[tid*1025 + 1024];
        float mp = s_ch[tid]     / fmaxf(cp, 1.f);   // dir0: queries = preds
        float mt = s_ch[B + tid] / fmaxf(ct, 1.f);   // dir1: queries = targets
        ch = (cp > 0.f && ct > 0.f) ? 0.5f * (mp + mt) : 0.f;
        a = g_ppart[tid*3+0]; c = g_ppart[tid*3+1]; d = g_ppart[tid*3+2];
    }
    if (tid < 32) {
        #pragma unroll
        for (int o = 16; o; o >>= 1) {
            ch += __shfl_xor_sync(0xffffffffu, ch, o);
            a  += __shfl_xor_sync(0xffffffffu, a,  o);
            c  += __shfl_xor_sync(0xffffffffu, c,  o);
            d  += __shfl_xor_sync(0xffffffffu, d,  o);
        }
        if (tid == 0) {
            float lc = ch / (float)B;
            float lp = a / (float)(B * N * 2);
            float ls = (c > 0.f) ? d / (float)(B * N * 2) : 0.f;
            out[0] = lp + 5.0f * lc + 2.0f * ls;
            out[1] = lp;
            out[2] = 0.f;
            out[3] = lc;
        }
    }
}

extern "C" void kernel_launch(void* const* d_in, const int* in_sizes, int n_in,
                              void* d_out, int out_size) {
    const float* pred   = (const float*)d_in[0];
    const float* target = (const float*)d_in[1];
    const float* smask  = (const float*)d_in[2];
    float* out = (float*)d_out;

    sk_bin_kernel<<<B, ATHREADS>>>(pred, target, smask);
    dim3 sgrid(QC, B, 2);
    sk_search_kernel<<<sgrid, STHREADS>>>(out);
}

// round 14
// speedup vs baseline: 2.1374x; 1.0366x over previous
#include <cuda_runtime.h>
#include <math.h>

#define B 32
#define N 2048
#define BN (B*N)

// binning
#define G 32
#define GG (G*G)
#define ORG  (-4.5f)
#define WBIN (9.0f / (float)G)
#define INVW ((float)G / 9.0f)

#define ATHREADS 256
#define QC 8                      // query chunks per (dir,b): 1 query/thread
#define STHREADS 256
#define SBLOCKS (QC*B*2)          // 512 search blocks

// ---------------- scratch (device globals; zero at module load) -------------
__device__ float2 g_Pb[BN], g_Tb[BN];        // binned visible points (CSR data)
__device__ int    g_offP[B*1025], g_offT[B*1025];  // CSR offsets + total at [1024]
__device__ float  g_ppart[B*3];              // {point,mask,struct} per batch
__device__ float  g_chpart[2*B*QC];          // per (dir,b,qc) sqrt-sums
__device__ int    g_fticket;                 // combine ticket (winner resets)

__device__ __forceinline__ int binc(float x) {
    int i = (int)floorf((x - ORG) * INVW);
    return min(max(i, 0), G - 1);
}

// exclusive scan of 1024 smem counters; writes offsets in place + to global[0..1024]
__device__ __forceinline__ void scan1024(unsigned* arr, unsigned* wsum, int* gout, int tid) {
    __syncthreads();
    int lane = tid & 31, wid = tid >> 5;
    unsigned v0 = arr[tid*4+0], v1 = arr[tid*4+1], v2 = arr[tid*4+2], v3 = arr[tid*4+3];
    unsigned tsum = v0 + v1 + v2 + v3;
    unsigned pre = tsum;
    #pragma unroll
    for (int o = 1; o < 32; o <<= 1) {
        unsigned nv = __shfl_up_sync(0xffffffffu, pre, o);
        if (lane >= o) pre += nv;
    }
    if (lane == 31) wsum[wid] = pre;
    unsigned texcl = pre - tsum;
    __syncthreads();
    if (tid == 0) {
        unsigned acc = 0;
        for (int w = 0; w < 8; w++) { unsigned x = wsum[w]; wsum[w] = acc; acc += x; }
        wsum[8] = acc;
    }
    __syncthreads();
    unsigned off = wsum[wid] + texcl;
    arr[tid*4+0] = off;      gout[tid*4+0] = (int)off;      off += v0;
    arr[tid*4+1] = off;      gout[tid*4+1] = (int)off;      off += v1;
    arr[tid*4+2] = off;      gout[tid*4+2] = (int)off;      off += v2;
    arr[tid*4+3] = off;      gout[tid*4+3] = (int)off;
    if (tid == 0) gout[1024] = (int)wsum[8];
    __syncthreads();
}

// ---------------- kernel A: per-role bin count + scan + scatter (+ losses) ---
__global__ void __launch_bounds__(ATHREADS) sk_bin_kernel(
        const float* __restrict__ pred,
        const float* __restrict__ target,
        const float* __restrict__ smask) {
    int b = blockIdx.x, role = blockIdx.y, tid = threadIdx.x;  // role 0=P, 1=T
    __shared__ unsigned s_cnt[GG];     // 4 KB
    __shared__ unsigned s_wsum[9];
    __shared__ float red[24];          // 8 warps x 3

    for (int i = tid; i < GG; i += ATHREADS) s_cnt[i] = 0;
    __syncthreads();

    const float* base = role ? target : pred;
    float s_point = 0.f, s_mask = 0.f, s_struct = 0.f;

    #pragma unroll
    for (int it = 0; it < N/ATHREADS; it++) {
        int n = it * ATHREADS + tid;
        int idx = b * N + n;
        float c0 = base[idx*3+0], c1 = base[idx*3+1], c2 = base[idx*3+2];
        bool vis = (c2 == 1.0f);
        if (vis) atomicAdd(&s_cnt[binc(c1)*G + binc(c0)], 1u);
        if (role && vis) {
            float p0 = pred[idx*3+0], p1 = pred[idx*3+1];
            float d0 = p0 - c0, d1 = p1 - c1;
            s_point += d0*d0 + d1*d1;
            float m0 = smask[idx*2+0], m1 = smask[idx*2+1];
            float sm = fminf(fmaxf(m0 + m1, 0.f), 1.f);
            s_mask += sm;
            float e0 = d0*sm, e1 = d1*sm;
            s_struct += e0*e0 + e1*e1;
        }
    }

    int* gout = (role ? g_offT : g_offP) + b*1025;
    scan1024(s_cnt, s_wsum, gout, tid);

    float2* gpts = (role ? g_Tb : g_Pb) + b*N;
    #pragma unroll
    for (int it = 0; it < N/ATHREADS; it++) {
        int n = it * ATHREADS + tid;
        int idx = b * N + n;
        float c0 = base[idx*3+0], c1 = base[idx*3+1], c2 = base[idx*3+2];
        if (c2 == 1.0f) {
            unsigned slot = atomicAdd(&s_cnt[binc(c1)*G + binc(c0)], 1u);
            gpts[slot] = make_float2(c0, c1);
        }
    }

    if (role) {
        #pragma unroll
        for (int o = 16; o; o >>= 1) {
            s_point  += __shfl_xor_sync(0xffffffffu, s_point,  o);
            s_mask   += __shfl_xor_sync(0xffffffffu, s_mask,   o);
            s_struct += __shfl_xor_sync(0xffffffffu, s_struct, o);
        }
        int lane = tid & 31, wid = tid >> 5;
        if (lane == 0) { red[wid] = s_point; red[8+wid] = s_mask; red[16+wid] = s_struct; }
        __syncthreads();
        if (tid == 0) {
            float a = 0.f, c = 0.f, d = 0.f;
            for (int w = 0; w < 8; w++) { a += red[w]; c += red[8+w]; d += red[16+w]; }
            g_ppart[b*3+0] = a; g_ppart[b*3+1] = c; g_ppart[b*3+2] = d;
        }
    }
}

// ---------------- kernel B: smem-staged 3x3-first search + fused combine -----
__global__ void __launch_bounds__(STHREADS) sk_search_kernel(float* __restrict__ out) {
    int qc = blockIdx.x, b = blockIdx.y, dir = blockIdx.z;
    int db = dir * B + b;
    int tid = threadIdx.x;

    const float2 *Qp, *Dp;
    const int *Qoff, *Doff;
    if (dir == 0) { Qp = g_Pb + b*N; Qoff = g_offP + b*1025; Dp = g_Tb + b*N; Doff = g_offT + b*1025; }
    else          { Qp = g_Tb + b*N; Qoff = g_offT + b*1025; Dp = g_Pb + b*N; Doff = g_offP + b*1025; }

    // stage whole database + offsets in shared memory
    __shared__ float2 s_D[N];        // 16 KB
    __shared__ int    s_off[1025];   // 4.1 KB
    #pragma unroll
    for (int it = 0; it < N/STHREADS; it++)
        s_D[it*STHREADS + tid] = Dp[it*STHREADS + tid];
    #pragma unroll
    for (int it = 0; it < 1025/STHREADS + 1; it++) {
        int i = it*STHREADS + tid;
        if (i < 1025) s_off[i] = Doff[i];
    }
    int cntQ = Qoff[1024];
    __syncthreads();

    float sum = 0.f;
    int q = qc * STHREADS + tid;
    if (q < cntQ) {
        float2 Qv = Qp[q];
        int qbx = binc(Qv.x), qby = binc(Qv.y);
        float best = 3.0e38f;

        auto scan_span = [&](int s, int e) {
            for (int k = s; k < e; k++) {
                float2 p = s_D[k];
                float dx = Qv.x - p.x, dy = Qv.y - p.y;
                float d2 = fmaf(dx, dx, dy*dy);
                best = fminf(best, d2);
            }
        };

        // unconditional merged 3x3 neighborhood (3 contiguous spans)
        {
            int i0 = max(qbx - 1, 0), i1 = min(qbx + 1, G-1);
            int j0 = max(qby - 1, 0), j1 = min(qby + 1, G-1);
            for (int j = j0; j <= j1; j++)
                scan_span(s_off[j*G + i0], s_off[j*G + i1 + 1]);
        }

        // rare outlier path: rings r >= 2 with lower-bound termination
        for (int r = 2; r < G; r++) {
            float bd = (float)(r-1) * WBIN;
            if (best <= bd*bd) break;
            int i0 = max(qbx - r, 0), i1 = min(qbx + r, G-1);
            int jt = qby - r, jb = qby + r;
            if (jt >= 0) scan_span(s_off[jt*G + i0], s_off[jt*G + i1 + 1]);
            if (jb < G)  scan_span(s_off[jb*G + i0], s_off[jb*G + i1 + 1]);
            int jj0 = max(qby - r + 1, 0), jj1 = min(qby + r - 1, G-1);
            if (qbx - r >= 0) {
                int ic = qbx - r;
                for (int j = jj0; j <= jj1; j++) scan_span(s_off[j*G + ic], s_off[j*G + ic + 1]);
            }
            if (qbx + r < G) {
                int ic = qbx + r;
                for (int j = jj0; j <= jj1; j++) scan_span(s_off[j*G + ic], s_off[j*G + ic + 1]);
            }
        }
        sum = sqrtf(fmaxf(best, 1e-12f));
    }

    // block reduction of sqrt-sum
    __shared__ float wred[8];
    #pragma unroll
    for (int o = 16; o; o >>= 1) sum += __shfl_xor_sync(0xffffffffu, sum, o);
    if ((tid & 31) == 0) wred[tid >> 5] = sum;
    __syncthreads();

    __shared__ int s_ft;
    if (tid == 0) {
        float tot = 0.f;
        #pragma unroll
        for (int w = 0; w < 8; w++) tot += wred[w];
        g_chpart[db*QC + qc] = tot;
        __threadfence();
        s_ft = atomicAdd(&g_fticket, 1);
    }
    __syncthreads();
    if (s_ft != SBLOCKS - 1) return;
    if (tid == 0) g_fticket = 0;          // reset for next replay
    __threadfence();

    // ---- combine (winner block) ---------------------------------------------
    __shared__ float s_ch[2*B];
    volatile float* vcp = g_chpart;
    if (tid < 2*B) {
        float s = 0.f;
        #pragma unroll
        for (int c = 0; c < QC; c++) s += vcp[tid*QC + c];
        s_ch[tid] = s;
    }
    __syncthreads();

    float ch = 0.f, a = 0.f, c = 0.f, d = 0.f;
    if (tid < B) {
        float cp = (float)g_offP[tid*1025 + 1024];
        float ct = (float)g_offT[tid*1025 + 1024];
        float mp = s_ch[tid]     / fmaxf(cp, 1.f);   // dir0: queries = preds
        float mt = s_ch[B + tid] / fmaxf(ct, 1.f);   // dir1: queries = targets
        ch = (cp > 0.f && ct > 0.f) ? 0.5f * (mp + mt) : 0.f;
        a = g_ppart[tid*3+0]; c = g_ppart[tid*3+1]; d = g_ppart[tid*3+2];
    }
    if (tid < 32) {
        #pragma unroll
        for (int o = 16; o; o >>= 1) {
            ch += __shfl_xor_sync(0xffffffffu, ch, o);
            a  += __shfl_xor_sync(0xffffffffu, a,  o);
            c  += __shfl_xor_sync(0xffffffffu, c,  o);
            d  += __shfl_xor_sync(0xffffffffu, d,  o);
        }
        if (tid == 0) {
            float lc = ch / (float)B;
            float lp = a / (float)(B * N * 2);
            float ls = (c > 0.f) ? d / (float)(B * N * 2) : 0.f;
            out[0] = lp + 5.0f * lc + 2.0f * ls;
            out[1] = lp;
            out[2] = 0.f;
            out[3] = lc;
        }
    }
}

extern "C" void kernel_launch(void* const* d_in, const int* in_sizes, int n_in,
                              void* d_out, int out_size) {
    const float* pred   = (const float*)d_in[0];
    const float* target = (const float*)d_in[1];
    const float* smask  = (const float*)d_in[2];
    float* out = (float*)d_out;

    dim3 agrid(B, 2);
    sk_bin_kernel<<<agrid, ATHREADS>>>(pred, target, smask);
    dim3 sgrid(QC, B, 2);
    sk_search_kernel<<<sgrid, STHREADS>>>(out);
}